// round 1
// baseline (speedup 1.0000x reference)
#include <cuda_runtime.h>
#include <cuda_bf16.h>
#include <cstdint>

// ---------------- scratch (no allocations allowed) ----------------
__device__ __nv_bfloat16 g_Yb[4096 * 6272];   // binarized layer-1 output, +-1 bf16
__device__ __nv_bfloat16 g_W2b[2048 * 6272];  // binarized W2, +-1 bf16
__device__ float        g_Z[4096 * 2048];     // layer-2 post-BN/clip activations

// ---------------- kernel 1: binarize W2 -> bf16 ----------------
__global__ void k_binW2(const float4* __restrict__ W2) {
    int i = blockIdx.x * blockDim.x + threadIdx.x;  // exactly 3211264 threads
    float4 v = W2[i];
    ushort4 o;
    o.x = v.x >= 0.f ? 0x3F80 : 0xBF80;
    o.y = v.y >= 0.f ? 0x3F80 : 0xBF80;
    o.z = v.z >= 0.f ? 0x3F80 : 0xBF80;
    o.w = v.w >= 0.f ? 0x3F80 : 0xBF80;
    *reinterpret_cast<ushort4*>(reinterpret_cast<unsigned short*>(g_W2b) + 4 * i) = o;
}

// ---------------- kernel 2: fused binconv + bias + maxpool + BN + sign ----------------
// one block per image, 256 threads (196 active for compute)
__global__ void k_conv(const float* __restrict__ x, const float* __restrict__ W1,
                       const float* __restrict__ b1, const float* __restrict__ g1,
                       const float* __restrict__ be1, const float* __restrict__ m1,
                       const float* __restrict__ v1) {
    __shared__ unsigned rows[28];
    __shared__ unsigned swb[32];
    __shared__ float sscale[32], soff[32], sbe[32];

    const int tid = threadIdx.x;
    const int b = blockIdx.x;

    if (tid < 28) rows[tid] = 0u;
    __syncthreads();

    if (tid < 196) {
        // 784 floats per image = 196 float4, 16B aligned
        float4 v = reinterpret_cast<const float4*>(x + b * 784)[tid];
        unsigned nib = (v.x >= 0.f ? 1u : 0u) | (v.y >= 0.f ? 2u : 0u) |
                       (v.z >= 0.f ? 4u : 0u) | (v.w >= 0.f ? 8u : 0u);
        int p0 = tid * 4;                 // 28 % 4 == 0 -> 4 pixels stay in one row
        atomicOr(&rows[p0 / 28], nib << (p0 % 28));
    }
    if (tid < 32) {
        unsigned w = 0;
#pragma unroll
        for (int t = 0; t < 9; t++) w |= (W1[tid * 9 + t] >= 0.f ? 1u : 0u) << t;
        swb[tid] = w;
        sscale[tid] = g1[tid] * rsqrtf(v1[tid] + 1e-5f);
        soff[tid] = b1[tid] - m1[tid];
        sbe[tid] = be1[tid];
    }
    __syncthreads();
    if (tid >= 196) return;

    const int py = tid / 14, px = tid % 14;
    unsigned pp[4], mm[4];
    int nn[4];
#pragma unroll
    for (int i = 0; i < 4; i++) {
        const int y = 2 * py + (i >> 1);
        const int xx = 2 * px + (i & 1);
        unsigned p = 0, mv = 0;
#pragma unroll
        for (int dy = 0; dy < 3; dy++) {
            int yy = y - 1 + dy;
            if (yy >= 0 && yy < 28) {
                unsigned rb = rows[yy];
                unsigned bits = (xx >= 1) ? ((rb >> (xx - 1)) & 7u) : ((rb << 1) & 7u);
                unsigned m3 = (xx == 0) ? 6u : ((xx == 27) ? 3u : 7u);
                p |= bits << (3 * dy);
                mv |= m3 << (3 * dy);
            }
        }
        pp[i] = p; mm[i] = mv; nn[i] = __popc(mv);
    }

    const __nv_bfloat16 POS = __float2bfloat16(1.0f);
    const __nv_bfloat16 NEG = __float2bfloat16(-1.0f);
    __nv_bfloat16* op = g_Yb + (size_t)b * 6272 + tid;
#pragma unroll
    for (int c = 0; c < 32; c++) {
        const unsigned w = swb[c];
        int best = -1000;
#pragma unroll
        for (int i = 0; i < 4; i++) {
            int d = __popc((pp[i] ^ w) & mm[i]);
            int val = nn[i] - 2 * d;            // exact conv sum of +-1 products
            best = val > best ? val : best;     // maxpool
        }
        float f = sscale[c] * ((float)best + soff[c]) + sbe[c];  // +bias, BN
        op[(size_t)c * 196] = (f >= 0.f) ? POS : NEG;            // sign(hardtanh(.)) = sign(.)
    }
}

// ---------------- kernel 3: bf16 GEMM  Z = Yb(4096x6272) * W2b^T + epilogue ----------------
__device__ __forceinline__ void ldsm4(unsigned& r0, unsigned& r1, unsigned& r2, unsigned& r3,
                                      const void* p) {
    unsigned a = (unsigned)__cvta_generic_to_shared(p);
    asm volatile("ldmatrix.sync.aligned.m8n8.x4.shared.b16 {%0,%1,%2,%3},[%4];"
                 : "=r"(r0), "=r"(r1), "=r"(r2), "=r"(r3) : "r"(a));
}
__device__ __forceinline__ void mma16816(float* d, const unsigned* a, unsigned b0, unsigned b1) {
    asm volatile(
        "mma.sync.aligned.m16n8k16.row.col.f32.bf16.bf16.f32 "
        "{%0,%1,%2,%3},{%4,%5,%6,%7},{%8,%9},{%0,%1,%2,%3};"
        : "+f"(d[0]), "+f"(d[1]), "+f"(d[2]), "+f"(d[3])
        : "r"(a[0]), "r"(a[1]), "r"(a[2]), "r"(a[3]), "r"(b0), "r"(b1));
}
__device__ __forceinline__ void cp16(const void* smem, const void* gmem) {
    unsigned sa = (unsigned)__cvta_generic_to_shared(smem);
    asm volatile("cp.async.cg.shared.global [%0],[%1],16;\n" ::"r"(sa), "l"(gmem) : "memory");
}

__global__ __launch_bounds__(256, 1) void k_gemm(const float* __restrict__ b2,
                                                 const float* __restrict__ g2,
                                                 const float* __restrict__ be2,
                                                 const float* __restrict__ m2,
                                                 const float* __restrict__ v2) {
    constexpr int STR = 40;  // halfs per smem row (80B, stride-5 in 16B units -> conflict-free ldmatrix)
    __shared__ __nv_bfloat16 sA[2][128 * STR];
    __shared__ __nv_bfloat16 sB[2][128 * STR];
    __shared__ float sS[128], sOf[128], sBe[128];

    const int tid = threadIdx.x, lane = tid & 31, warp = tid >> 5;
    const int m0 = blockIdx.y * 128, n0 = blockIdx.x * 128;
    const int wm = warp >> 1, wn = warp & 1;  // warp tile: 32(m) x 64(n)

    if (tid < 128) {
        int h = n0 + tid;
        sS[tid] = g2[h] * rsqrtf(v2[h] + 1e-5f);
        sOf[tid] = b2[h] - m2[h];
        sBe[tid] = be2[h];
    }

    float acc[2][8][4];
#pragma unroll
    for (int i = 0; i < 2; i++)
#pragma unroll
        for (int j = 0; j < 8; j++)
#pragma unroll
            for (int q = 0; q < 4; q++) acc[i][j][q] = 0.f;

    auto loadTile = [&](int buf, int kt) {
        const int k0 = kt * 32;
        const int r = tid >> 2, c = tid & 3;
#pragma unroll
        for (int p = 0; p < 2; p++) {
            int rr = r + p * 64;
            cp16(&sA[buf][rr * STR + c * 8], g_Yb + (size_t)(m0 + rr) * 6272 + k0 + c * 8);
            cp16(&sB[buf][rr * STR + c * 8], g_W2b + (size_t)(n0 + rr) * 6272 + k0 + c * 8);
        }
    };

    loadTile(0, 0);
    asm volatile("cp.async.commit_group;\n" ::: "memory");

    int cur = 0;
    for (int kt = 0; kt < 196; ++kt) {
        if (kt < 195) {
            loadTile(cur ^ 1, kt + 1);
            asm volatile("cp.async.commit_group;\n" ::: "memory");
            asm volatile("cp.async.wait_group 1;\n" ::: "memory");
        } else {
            asm volatile("cp.async.wait_group 0;\n" ::: "memory");
        }
        __syncthreads();

#pragma unroll
        for (int kk = 0; kk < 2; kk++) {
            unsigned a[2][4];
#pragma unroll
            for (int i = 0; i < 2; i++) {
                const __nv_bfloat16* ptr =
                    &sA[cur][(wm * 32 + i * 16 + (lane & 15)) * STR + kk * 16 + (lane >> 4) * 8];
                ldsm4(a[i][0], a[i][1], a[i][2], a[i][3], ptr);
            }
#pragma unroll
            for (int j4 = 0; j4 < 4; j4++) {
                unsigned bb[4];
                const __nv_bfloat16* ptr =
                    &sB[cur][(wn * 64 + j4 * 16 + (lane & 15)) * STR + kk * 16 + (lane >> 4) * 8];
                ldsm4(bb[0], bb[1], bb[2], bb[3], ptr);
#pragma unroll
                for (int i = 0; i < 2; i++) {
                    mma16816(acc[i][j4 * 2 + 0], a[i], bb[0], bb[2]);
                    mma16816(acc[i][j4 * 2 + 1], a[i], bb[1], bb[3]);
                }
            }
        }
        __syncthreads();
        cur ^= 1;
    }

    // epilogue: +b2, BN, clip -> g_Z
#pragma unroll
    for (int i = 0; i < 2; i++) {
        const int mr = m0 + wm * 32 + i * 16 + (lane >> 2);
#pragma unroll
        for (int j = 0; j < 8; j++) {
            const int nl = wn * 64 + j * 8 + (lane & 3) * 2;
            float s0 = sS[nl], s1 = sS[nl + 1];
            float o0 = sOf[nl], o1 = sOf[nl + 1];
            float e0 = sBe[nl], e1 = sBe[nl + 1];
            float* zp0 = &g_Z[(size_t)mr * 2048 + n0 + nl];
            float* zp1 = zp0 + 8 * 2048;
            float z;
            z = (acc[i][j][0] + o0) * s0 + e0; zp0[0] = fminf(1.f, fmaxf(-1.f, z));
            z = (acc[i][j][1] + o1) * s1 + e1; zp0[1] = fminf(1.f, fmaxf(-1.f, z));
            z = (acc[i][j][2] + o0) * s0 + e0; zp1[0] = fminf(1.f, fmaxf(-1.f, z));
            z = (acc[i][j][3] + o1) * s1 + e1; zp1[1] = fminf(1.f, fmaxf(-1.f, z));
        }
    }
}

// ---------------- kernel 4: logits + log_softmax ----------------
__global__ __launch_bounds__(256) void k_head(const float* __restrict__ W3,
                                              const float* __restrict__ b3,
                                              float* __restrict__ out) {
    __shared__ float red[8][40];
    __shared__ float fin[40];
    const int tid = threadIdx.x, lane = tid & 31, warp = tid >> 5;
    const int b0 = blockIdx.x * 4;

    float acc[40];
#pragma unroll
    for (int i = 0; i < 40; i++) acc[i] = 0.f;

    for (int f = tid; f < 2048; f += 256) {
        float zv[4];
#pragma unroll
        for (int r = 0; r < 4; r++) zv[r] = g_Z[(size_t)(b0 + r) * 2048 + f];
#pragma unroll
        for (int c = 0; c < 10; c++) {
            float w = W3[c * 2048 + f];
#pragma unroll
            for (int r = 0; r < 4; r++) acc[r * 10 + c] += zv[r] * w;
        }
    }
#pragma unroll
    for (int i = 0; i < 40; i++)
#pragma unroll
        for (int o = 16; o > 0; o >>= 1) acc[i] += __shfl_down_sync(0xffffffffu, acc[i], o);
    if (lane == 0)
#pragma unroll
        for (int i = 0; i < 40; i++) red[warp][i] = acc[i];
    __syncthreads();
    if (tid < 40) {
        float s = 0.f;
#pragma unroll
        for (int w = 0; w < 8; w++) s += red[w][tid];
        fin[tid] = s + b3[tid % 10];
    }
    __syncthreads();
    if (tid < 4) {
        float mx = -1e30f;
#pragma unroll
        for (int c = 0; c < 10; c++) mx = fmaxf(mx, fin[tid * 10 + c]);
        float se = 0.f;
#pragma unroll
        for (int c = 0; c < 10; c++) se += expf(fin[tid * 10 + c] - mx);
        float ls = mx + logf(se);
#pragma unroll
        for (int c = 0; c < 10; c++) out[(size_t)(b0 + tid) * 10 + c] = fin[tid * 10 + c] - ls;
    }
}

// ---------------- launch ----------------
extern "C" void kernel_launch(void* const* d_in, const int* in_sizes, int n_in,
                              void* d_out, int out_size) {
    const float* x   = (const float*)d_in[0];
    const float* W1  = (const float*)d_in[1];
    const float* b1  = (const float*)d_in[2];
    const float* g1  = (const float*)d_in[3];
    const float* be1 = (const float*)d_in[4];
    const float* m1  = (const float*)d_in[5];
    const float* v1  = (const float*)d_in[6];
    const float* W2  = (const float*)d_in[7];
    const float* b2  = (const float*)d_in[8];
    const float* g2  = (const float*)d_in[9];
    const float* be2 = (const float*)d_in[10];
    const float* m2  = (const float*)d_in[11];
    const float* v2  = (const float*)d_in[12];
    const float* W3  = (const float*)d_in[13];
    const float* b3  = (const float*)d_in[14];

    k_binW2<<<12544, 256>>>((const float4*)W2);              // 2048*6272/4/256
    k_conv<<<4096, 256>>>(x, W1, b1, g1, be1, m1, v1);
    dim3 gg(16, 32);                                          // N/128, M/128
    k_gemm<<<gg, 256>>>(b2, g2, be2, m2, v2);
    k_head<<<1024, 256>>>(W3, b3, (float*)d_out);
}